// round 4
// baseline (speedup 1.0000x reference)
#include <cuda_runtime.h>
#include <cstdint>

#define NN   40000
#define EE   400000
#define EP   (EE + NN)
#define HH   8
#define HC   512
#define FF   16
#define RR   40
#define KOUT 39
#define WCOL 61
#define NLOG (RR * RR * KOUT)
#define NCH  40
#define AGG_NODES 136          // nodes per k_agg block (296 blocks)
#define AGG_BLOCKS 296
#define SM_AGG_FLOATS (RR * HC)        // 20480
#define SM_W_FLOATS   (8 * RR * HH)    // 2560
#define SMEM_AGG_BYTES ((SM_AGG_FLOATS + SM_W_FLOATS) * 4 + 64)

// ---------------- scratch ---------------------------------------------------
__device__ float g_h[(size_t)NN * HC];        // 82 MB
__device__ float g_as[NN * HH];
__device__ float g_ad[NN * HH];
__device__ float g_exs[(size_t)EP * HH];      // src-sorted exp values
__device__ float g_denom[NN * HH];            // then inverted in place
__device__ int   g_deg[NN];
__device__ int   g_rowptr[NN + 1];
__device__ int   g_cursor[NN];
__device__ int   g_dsts[EP];                  // src-sorted dst ids
__device__ int   g_bsum[NCH];
__device__ int   g_boff[NCH];
__device__ float g_agg[2][RR * HC];
__device__ int   g_cnt[2][RR];
__device__ float g_U[2][RR * 64];
__device__ float g_logits[NLOG];

__device__ __forceinline__ void red4(float* p, float4 v) {
    asm volatile("red.global.add.v4.f32 [%0], {%1, %2, %3, %4};"
                 :: "l"(p), "f"(v.x), "f"(v.y), "f"(v.z), "f"(v.w) : "memory");
}

// ---------------- one-time zero of route accumulators -----------------------
__global__ void k_zero_all() {
    int i = blockIdx.x * blockDim.x + threadIdx.x;
    if (i < 2 * RR * HC) ((float*)g_agg)[i] = 0.f;
    if (i < 2 * RR)      ((int*)g_cnt)[i] = 0;
}

// ---------------- per-graph init --------------------------------------------
__global__ void k_init(int g, const int* __restrict__ route_vec) {
    int i = blockIdx.x * blockDim.x + threadIdx.x;
    if (i < NN) {
        g_deg[i] = 1;                       // self loop (out-degree)
        atomicAdd(&g_cnt[g][route_vec[i]], 1);
        float4* d4 = (float4*)(g_denom + i * HH);
        d4[0] = make_float4(0,0,0,0);
        d4[1] = make_float4(0,0,0,0);
    }
}

// ---------------- fused GEMM h = x@W + attention dots -----------------------
__global__ __launch_bounds__(256) void k_gemm(
    const float* __restrict__ x, const float* __restrict__ W,
    const float* __restrict__ attS, const float* __restrict__ attD)
{
    __shared__ float Wsh[FF * HC];
    int t = threadIdx.x;
    for (int i = t; i < FF * HC; i += blockDim.x) Wsh[i] = W[i];
    __syncthreads();

    int l    = t & 31;
    int wid  = blockIdx.x * (blockDim.x >> 5) + (t >> 5);
    int nwrp = gridDim.x * (blockDim.x >> 5);

    for (int n = wid; n < NN; n += nwrp) {
        float v = (l < FF) ? x[n * FF + l] : 0.f;
        float xr[FF];
        #pragma unroll
        for (int f = 0; f < FF; f++) xr[f] = __shfl_sync(0xffffffffu, v, f);

        float hacc[16];
        #pragma unroll
        for (int k = 0; k < 16; k++) {
            float a = 0.f;
            #pragma unroll
            for (int f = 0; f < FF; f++)
                a = fmaf(xr[f], Wsh[f * HC + 32 * k + l], a);
            hacc[k] = a;
            g_h[(size_t)n * HC + 32 * k + l] = a;
        }
        #pragma unroll
        for (int h = 0; h < HH; h++) {
            float ps = fmaf(hacc[2*h],   attS[h*64 + l],
                      hacc[2*h+1] * attS[h*64 + 32 + l]);
            float pd = fmaf(hacc[2*h],   attD[h*64 + l],
                      hacc[2*h+1] * attD[h*64 + 32 + l]);
            #pragma unroll
            for (int o = 16; o > 0; o >>= 1) {
                ps += __shfl_xor_sync(0xffffffffu, ps, o);
                pd += __shfl_xor_sync(0xffffffffu, pd, o);
            }
            if (l == 0) { g_as[n*HH + h] = ps; g_ad[n*HH + h] = pd; }
        }
    }
}

// ---------------- out-degree histogram (src column) -------------------------
__global__ void k_deg(const int* __restrict__ ei) {
    int i = blockIdx.x * blockDim.x + threadIdx.x;
    if (i < EE) atomicAdd(&g_deg[ei[i]], 1);
}

// ---------------- parallel 3-stage scan -------------------------------------
__global__ void k_blocksum() {
    __shared__ int s[1024];
    int b = blockIdx.x, t = threadIdx.x;
    int i = b * 1024 + t;
    s[t] = (i < NN) ? g_deg[i] : 0;
    __syncthreads();
    for (int off = 512; off > 0; off >>= 1) {
        if (t < off) s[t] += s[t + off];
        __syncthreads();
    }
    if (t == 0) g_bsum[b] = s[0];
}

__global__ void k_bscan() {
    int c = 0;
    #pragma unroll
    for (int b = 0; b < NCH; b++) { g_boff[b] = c; c += g_bsum[b]; }
    g_rowptr[NN] = c;
}

__global__ void k_offsets() {
    __shared__ int s[1024];
    int b = blockIdx.x, t = threadIdx.x;
    int i = b * 1024 + t;
    int v = (i < NN) ? g_deg[i] : 0;
    s[t] = v;
    __syncthreads();
    for (int off = 1; off < 1024; off <<= 1) {
        int a = (t >= off) ? s[t - off] : 0;
        __syncthreads();
        s[t] += a;
        __syncthreads();
    }
    if (i < NN) {
        int ex = g_boff[b] + s[t] - v;
        g_rowptr[i] = ex;
        g_cursor[i] = ex;
    }
}

// ---------------- fused scatter (sort by SRC) + edge exp + denom ------------
// No max-shift: attention logits ~N(0,2); exp safe in fp32, alpha invariant.
__global__ void k_scatter_edges(const int* __restrict__ ei) {
    int i = blockIdx.x * blockDim.x + threadIdx.x;
    if (i >= EP) return;
    int src, dst;
    if (i < EE) { src = ei[i]; dst = ei[EE + i]; }
    else        { src = i - EE; dst = src; }

    const float4* as4 = (const float4*)(g_as + src * HH);
    const float4* ad4 = (const float4*)(g_ad + dst * HH);
    float4 r[2];
    #pragma unroll
    for (int p = 0; p < 2; p++) {
        float4 a = as4[p], b = ad4[p];
        float e0 = a.x + b.x, e1 = a.y + b.y, e2 = a.z + b.z, e3 = a.w + b.w;
        e0 = e0 > 0.f ? e0 : 0.2f * e0;
        e1 = e1 > 0.f ? e1 : 0.2f * e1;
        e2 = e2 > 0.f ? e2 : 0.2f * e2;
        e3 = e3 > 0.f ? e3 : 0.2f * e3;
        r[p] = make_float4(__expf(e0), __expf(e1), __expf(e2), __expf(e3));
    }
    int pos = atomicAdd(&g_cursor[src], 1);
    g_dsts[pos] = dst;
    float4* exo = (float4*)(g_exs + (size_t)pos * HH);
    exo[0] = r[0];
    exo[1] = r[1];
    red4(&g_denom[dst * HH],     r[0]);
    red4(&g_denom[dst * HH + 4], r[1]);
}

// ---------------- invert denom in place -------------------------------------
__global__ void k_dinv() {
    int i = blockIdx.x * blockDim.x + threadIdx.x;
    if (i < NN * HH) g_denom[i] = 1.f / g_denom[i];
}

// ---------------- route aggregation: streamed h, smem accumulator -----------
// agg[r][c] = sum_src h[src][c] * w[src][r][head(c)],
// w[src][r][h] = sum_{edges src->dst, route(dst)=r} ex / denom[dst]
__global__ __launch_bounds__(256) void k_agg(int g, const int* __restrict__ route_vec) {
    extern __shared__ float sm[];
    float*    sAgg  = sm;                         // 20480 floats
    float*    sW    = sm + SM_AGG_FLOATS;         // 8 warps x 320
    unsigned* sMask = (unsigned*)(sm + SM_AGG_FLOATS + SM_W_FLOATS); // 16

    int t = threadIdx.x, l = t & 31, w = t >> 5;
    for (int i = t; i < SM_AGG_FLOATS + SM_W_FLOATS; i += 256) sm[i] = 0.f;
    if (t < 16) sMask[t] = 0;
    __syncthreads();

    int n0 = blockIdx.x * AGG_NODES;
    int n1 = n0 + AGG_NODES; if (n1 > NN) n1 = NN;
    float*    myW = sW + w * (RR * HH);
    unsigned* myM = sMask + w * 2;

    for (int n = n0 + w; n < n1; n += 8) {
        int start = g_rowptr[n], end = g_rowptr[n + 1];

        // --- edge phase: build sparse per-route weights for this src ---
        for (int j = start + l; j < end; j += 32) {
            int dst = g_dsts[j];
            int rt  = route_vec[dst];
            float4 e0 = ((const float4*)g_exs)[(size_t)j * 2];
            float4 e1 = ((const float4*)g_exs)[(size_t)j * 2 + 1];
            float4 d0 = ((const float4*)g_denom)[dst * 2];      // 1/denom
            float4 d1 = ((const float4*)g_denom)[dst * 2 + 1];
            float* wp = myW + rt * 8;
            atomicAdd(wp + 0, e0.x * d0.x); atomicAdd(wp + 1, e0.y * d0.y);
            atomicAdd(wp + 2, e0.z * d0.z); atomicAdd(wp + 3, e0.w * d0.w);
            atomicAdd(wp + 4, e1.x * d1.x); atomicAdd(wp + 5, e1.y * d1.y);
            atomicAdd(wp + 6, e1.z * d1.z); atomicAdd(wp + 7, e1.w * d1.w);
            atomicOr(&myM[rt >> 5], 1u << (rt & 31));
        }
        __syncwarp();

        // --- h row: fully coalesced, lane l gets channels k*128 + l*4 ---
        const float4* h4 = (const float4*)(g_h + (size_t)n * HC);
        float4 hv0 = h4[l], hv1 = h4[32 + l], hv2 = h4[64 + l], hv3 = h4[96 + l];
        int hs = (l >> 4);   // head(k) = 2k + hs

        unsigned m0 = myM[0], m1 = myM[1];
        __syncwarp();
        while (m0 | m1) {
            int r;
            if (m0) { r = __ffs(m0) - 1;      m0 &= m0 - 1; }
            else    { r = 31 + __ffs(m1);     m1 &= m1 - 1; }
            float w0 = myW[r * 8 + 0 + hs];
            float w1 = myW[r * 8 + 2 + hs];
            float w2 = myW[r * 8 + 4 + hs];
            float w3 = myW[r * 8 + 6 + hs];
            float* ap = sAgg + r * HC + l * 4;
            atomicAdd(ap + 0,   w0 * hv0.x); atomicAdd(ap + 1,   w0 * hv0.y);
            atomicAdd(ap + 2,   w0 * hv0.z); atomicAdd(ap + 3,   w0 * hv0.w);
            atomicAdd(ap + 128, w1 * hv1.x); atomicAdd(ap + 129, w1 * hv1.y);
            atomicAdd(ap + 130, w1 * hv1.z); atomicAdd(ap + 131, w1 * hv1.w);
            atomicAdd(ap + 256, w2 * hv2.x); atomicAdd(ap + 257, w2 * hv2.y);
            atomicAdd(ap + 258, w2 * hv2.z); atomicAdd(ap + 259, w2 * hv2.w);
            atomicAdd(ap + 384, w3 * hv3.x); atomicAdd(ap + 385, w3 * hv3.y);
            atomicAdd(ap + 386, w3 * hv3.z); atomicAdd(ap + 387, w3 * hv3.w);
            __syncwarp();
            if (l < 8) myW[r * 8 + l] = 0.f;    // rezero used entries
            __syncwarp();
        }
        if (l < 2) myM[l] = 0;
        __syncwarp();
    }
    __syncthreads();

    // --- flush block accumulator ---
    float* dstbase = (float*)g_agg + g * (RR * HC);
    for (int i = t; i < SM_AGG_FLOATS / 4; i += 256) {
        float4 v = ((float4*)sAgg)[i];
        red4(dstbase + i * 4, v);
    }
}

// ---------------- U[which][r][k] = (agg + cnt*bias) . W_head_slice ----------
__global__ void k_U(const float* __restrict__ bias, const float* __restrict__ Whead) {
    __shared__ float sA[HC];
    int b = blockIdx.x;
    int which = b & 1;
    int r     = b >> 1;
    int t = threadIdx.x;
    float cnt = (float)g_cnt[which][r];
    for (int c = t; c < HC; c += blockDim.x)
        sA[c] = g_agg[which][r * HC + c] + cnt * bias[c];
    __syncthreads();
    if (t < KOUT) {
        float acc = 0.f;
        for (int c = 0; c < HC; c++)
            acc = fmaf(sA[c], Whead[(size_t)(which * HC + c) * WCOL + t], acc);
        g_U[which][r * 64 + t] = acc;
    }
}

// ---------------- logits -----------------------------------------------------
__global__ void k_logits(const float* __restrict__ bh) {
    int i = blockIdx.x * blockDim.x + threadIdx.x;
    if (i >= NLOG) return;
    int k  = i % KOUT;
    int r2 = (i / KOUT) % RR;
    int r1 = i / (KOUT * RR);
    g_logits[i] = g_U[0][r1 * 64 + k] + g_U[1][r2 * 64 + k] + bh[k];
}

// ---------------- global softmax --------------------------------------------
__global__ void k_softmax(float* __restrict__ out) {
    __shared__ float s[1024];
    __shared__ float gm_sh, gs_sh;
    int t = threadIdx.x;

    float m = -1e30f;
    for (int i = t; i < NLOG; i += 1024) m = fmaxf(m, g_logits[i]);
    s[t] = m; __syncthreads();
    for (int off = 512; off > 0; off >>= 1) {
        if (t < off) s[t] = fmaxf(s[t], s[t + off]);
        __syncthreads();
    }
    if (t == 0) gm_sh = s[0];
    __syncthreads();
    float gm = gm_sh;
    __syncthreads();

    float sum = 0.f;
    for (int i = t; i < NLOG; i += 1024) sum += expf(g_logits[i] - gm);
    s[t] = sum; __syncthreads();
    for (int off = 512; off > 0; off >>= 1) {
        if (t < off) s[t] += s[t + off];
        __syncthreads();
    }
    if (t == 0) gs_sh = s[0];
    __syncthreads();
    float inv = 1.f / gs_sh;

    for (int i = t; i < NLOG; i += 1024)
        out[i] = expf(g_logits[i] - gm) * inv;
}

// ---------------- launch -----------------------------------------------------
extern "C" void kernel_launch(void* const* d_in, const int* in_sizes, int n_in,
                              void* d_out, int out_size) {
    const float* x1   = (const float*)d_in[0];
    const int*   ei1  = (const int*)  d_in[1];
    const int*   rv1  = (const int*)  d_in[3];
    const float* x2   = (const float*)d_in[5];
    const int*   ei2  = (const int*)  d_in[6];
    const int*   rv2  = (const int*)  d_in[8];
    const float* Wg   = (const float*)d_in[10];
    const float* atS  = (const float*)d_in[11];
    const float* atD  = (const float*)d_in[12];
    const float* bg   = (const float*)d_in[13];
    const float* Wh   = (const float*)d_in[14];
    const float* bh   = (const float*)d_in[15];
    float* out = (float*)d_out;

    cudaFuncSetAttribute(k_agg, cudaFuncAttributeMaxDynamicSharedMemorySize,
                         SMEM_AGG_BYTES);

    const int TB = 256;
    const int GN  = (NN + TB - 1) / TB;
    const int GE  = (EE + TB - 1) / TB;
    const int GEP = (EP + TB - 1) / TB;
    const int GNH = (NN * HH + TB - 1) / TB;
    const int GEMM_BLOCKS = 592;

    const float* xs[2]  = { x1, x2 };
    const int*   eis[2] = { ei1, ei2 };
    const int*   rvs[2] = { rv1, rv2 };

    k_zero_all<<<(2 * RR * HC + TB - 1) / TB, TB>>>();

    for (int g = 0; g < 2; g++) {
        k_init<<<GN, TB>>>(g, rvs[g]);
        k_gemm<<<GEMM_BLOCKS, TB>>>(xs[g], Wg, atS, atD);
        k_deg<<<GE, TB>>>(eis[g]);
        k_blocksum<<<NCH, 1024>>>();
        k_bscan<<<1, 1>>>();
        k_offsets<<<NCH, 1024>>>();
        k_scatter_edges<<<GEP, TB>>>(eis[g]);
        k_dinv<<<GNH, TB>>>();
        k_agg<<<AGG_BLOCKS, TB, SMEM_AGG_BYTES>>>(g, rvs[g]);
    }
    k_U<<<2 * RR, 128>>>(bg, Wh);
    k_logits<<<(NLOG + TB - 1) / TB, TB>>>(bh);
    k_softmax<<<1, 1024>>>(out);
    (void)in_sizes; (void)n_in; (void)out_size;
}

// round 14
// speedup vs baseline: 5.4345x; 5.4345x over previous
#include <cuda_runtime.h>
#include <cstdint>

#define NN   40000
#define EE   400000
#define EP   (EE + NN)
#define HH   8
#define HC   512
#define FF   16
#define RR   40
#define KOUT 39
#define WCOL 61
#define NLOG (RR * RR * KOUT)
#define NCH  40

// ---------------- scratch ---------------------------------------------------
__device__ float g_as[NN * HH];
__device__ float g_ad[NN * HH];
__device__ int   g_deg[NN];
__device__ int   g_rowptr[NN + 1];
__device__ int   g_cursor[NN];
__device__ int   g_srcs[EP];               // dst-sorted src ids
__device__ int   g_bsum[NCH];
__device__ int   g_boff[NCH];
__device__ float g_va[FF * HH];            // W@att_src  (f-major: [f][h])
__device__ float g_vd[FF * HH];            // W@att_dst
__device__ float g_ragg[2][RR * HH * FF];  // route-level alpha-weighted x sums
__device__ int   g_cnt[2][RR];
__device__ float g_U[2][RR * 64];
__device__ float g_logits[NLOG];

__device__ __forceinline__ void red4(float* p, float4 v) {
    asm volatile("red.global.add.v4.f32 [%0], {%1, %2, %3, %4};"
                 :: "l"(p), "f"(v.x), "f"(v.y), "f"(v.z), "f"(v.w) : "memory");
}

// ---------------- one-time zeroing ------------------------------------------
__global__ void k_zero_all() {
    int i = blockIdx.x * blockDim.x + threadIdx.x;
    if (i < 2 * RR * HH * FF) ((float*)g_ragg)[i] = 0.f;
    if (i < 2 * RR)           ((int*)g_cnt)[i] = 0;
}

// ---------------- precompute va/vd = W contracted with att ------------------
__global__ void k_prep(const float* __restrict__ W,
                       const float* __restrict__ attS,
                       const float* __restrict__ attD) {
    int t = threadIdx.x;           // 128 threads: t = f*8 + h
    int f = t >> 3, h = t & 7;
    float sa = 0.f, sd = 0.f;
    const float* wrow = W + f * HC + h * 64;
    const float* as = attS + h * 64;
    const float* ad = attD + h * 64;
    #pragma unroll
    for (int c = 0; c < 64; c++) {
        float w = wrow[c];
        sa = fmaf(w, as[c], sa);
        sd = fmaf(w, ad[c], sd);
    }
    g_va[t] = sa;
    g_vd[t] = sd;
}

// ---------------- attention scores + per-graph init (fused) -----------------
__global__ __launch_bounds__(256) void k_att(int g, const float* __restrict__ x,
                                             const int* __restrict__ route_vec) {
    __shared__ float sva[FF * HH], svd[FF * HH];
    int t = threadIdx.x;
    if (t < FF * HH) { sva[t] = g_va[t]; svd[t] = g_vd[t]; }
    __syncthreads();

    int n = blockIdx.x * blockDim.x + t;
    if (n >= NN) return;

    g_deg[n] = 1;   // self loop
    atomicAdd(&g_cnt[g][route_vec[n]], 1);

    const float4* x4 = (const float4*)(x + n * FF);
    float4 v0 = x4[0], v1 = x4[1], v2 = x4[2], v3 = x4[3];
    float xr[FF] = { v0.x, v0.y, v0.z, v0.w, v1.x, v1.y, v1.z, v1.w,
                     v2.x, v2.y, v2.z, v2.w, v3.x, v3.y, v3.z, v3.w };
    float as[HH], ad[HH];
    #pragma unroll
    for (int h = 0; h < HH; h++) { as[h] = 0.f; ad[h] = 0.f; }
    #pragma unroll
    for (int f = 0; f < FF; f++) {
        #pragma unroll
        for (int h = 0; h < HH; h++) {
            as[h] = fmaf(xr[f], sva[f * HH + h], as[h]);
            ad[h] = fmaf(xr[f], svd[f * HH + h], ad[h]);
        }
    }
    float4* o = (float4*)(g_as + n * HH);
    o[0] = make_float4(as[0], as[1], as[2], as[3]);
    o[1] = make_float4(as[4], as[5], as[6], as[7]);
    float4* o2 = (float4*)(g_ad + n * HH);
    o2[0] = make_float4(ad[0], ad[1], ad[2], ad[3]);
    o2[1] = make_float4(ad[4], ad[5], ad[6], ad[7]);
}

// ---------------- in-degree histogram (dst column) --------------------------
__global__ void k_deg(const int* __restrict__ ei) {
    int i = blockIdx.x * blockDim.x + threadIdx.x;
    if (i < EE) atomicAdd(&g_deg[ei[EE + i]], 1);
}

// ---------------- parallel 3-stage scan -------------------------------------
__global__ void k_blocksum() {
    __shared__ int s[1024];
    int b = blockIdx.x, t = threadIdx.x;
    int i = b * 1024 + t;
    s[t] = (i < NN) ? g_deg[i] : 0;
    __syncthreads();
    for (int off = 512; off > 0; off >>= 1) {
        if (t < off) s[t] += s[t + off];
        __syncthreads();
    }
    if (t == 0) g_bsum[b] = s[0];
}

__global__ void k_bscan() {
    int c = 0;
    #pragma unroll
    for (int b = 0; b < NCH; b++) { g_boff[b] = c; c += g_bsum[b]; }
    g_rowptr[NN] = c;
}

__global__ void k_offsets() {
    __shared__ int s[1024];
    int b = blockIdx.x, t = threadIdx.x;
    int i = b * 1024 + t;
    int v = (i < NN) ? g_deg[i] : 0;
    s[t] = v;
    __syncthreads();
    for (int off = 1; off < 1024; off <<= 1) {
        int a = (t >= off) ? s[t - off] : 0;
        __syncthreads();
        s[t] += a;
        __syncthreads();
    }
    if (i < NN) {
        int ex = g_boff[b] + s[t] - v;
        g_rowptr[i] = ex;
        g_cursor[i] = ex;
    }
}

// ---------------- counting sort by dst (src ids only) -----------------------
__global__ void k_scatter(const int* __restrict__ ei) {
    int i = blockIdx.x * blockDim.x + threadIdx.x;
    if (i >= EP) return;
    int src, dst;
    if (i < EE) { src = ei[i]; dst = ei[EE + i]; }
    else        { src = i - EE; dst = src; }
    int pos = atomicAdd(&g_cursor[dst], 1);
    g_srcs[pos] = src;
}

// ---------------- aggregation in x-domain: warp per dst ---------------------
// Lanes 0..7 recompute ex = exp(leaky_relu(a_s[src][l] + a_d[dst][l])) on the
// fly (g_as is 1.25 MB, L1/L2-resident). No max-shift: logits ~N(0,2), exp is
// fp32-safe and alpha = ex/denom is shift-invariant.
// Lane l accumulates head l>>2, features (l&3)*4..+3 => flat offset 4*l.
__global__ __launch_bounds__(256) void k_emb(int g, const float* __restrict__ x,
                                             const int* __restrict__ route_vec) {
    int warp = threadIdx.x >> 5;
    int l    = threadIdx.x & 31;
    int dst  = blockIdx.x * 8 + warp;
    if (dst >= NN) return;

    int start = g_rowptr[dst];
    int end   = g_rowptr[dst + 1];

    float adv = (l < HH) ? g_ad[dst * HH + l] : 0.f;   // per-head dst term
    float4 acc = make_float4(0.f, 0.f, 0.f, 0.f);
    float dsum = 0.f;                 // lanes 0..7: denom for head l
    int fq = l & 3;

    int j = start;
    for (; j + 3 < end; j += 4) {
        int s0 = g_srcs[j], s1 = g_srcs[j + 1], s2 = g_srcs[j + 2], s3 = g_srcs[j + 3];
        float t0 = 0.f, t1 = 0.f, t2 = 0.f, t3 = 0.f;
        if (l < HH) {
            t0 = g_as[s0 * HH + l] + adv;
            t1 = g_as[s1 * HH + l] + adv;
            t2 = g_as[s2 * HH + l] + adv;
            t3 = g_as[s3 * HH + l] + adv;
        }
        t0 = t0 > 0.f ? t0 : 0.2f * t0;
        t1 = t1 > 0.f ? t1 : 0.2f * t1;
        t2 = t2 > 0.f ? t2 : 0.2f * t2;
        t3 = t3 > 0.f ? t3 : 0.2f * t3;
        float e0 = __expf(t0), e1 = __expf(t1), e2 = __expf(t2), e3 = __expf(t3);
        if (l >= HH) { e0 = e1 = e2 = e3 = 0.f; }
        dsum += (e0 + e1) + (e2 + e3);
        float ea0 = __shfl_sync(0xffffffffu, e0, l >> 2);
        float ea1 = __shfl_sync(0xffffffffu, e1, l >> 2);
        float ea2 = __shfl_sync(0xffffffffu, e2, l >> 2);
        float ea3 = __shfl_sync(0xffffffffu, e3, l >> 2);
        float4 xv0 = ((const float4*)(x + s0 * FF))[fq];
        float4 xv1 = ((const float4*)(x + s1 * FF))[fq];
        float4 xv2 = ((const float4*)(x + s2 * FF))[fq];
        float4 xv3 = ((const float4*)(x + s3 * FF))[fq];
        acc.x = fmaf(ea0, xv0.x, acc.x); acc.y = fmaf(ea0, xv0.y, acc.y);
        acc.z = fmaf(ea0, xv0.z, acc.z); acc.w = fmaf(ea0, xv0.w, acc.w);
        acc.x = fmaf(ea1, xv1.x, acc.x); acc.y = fmaf(ea1, xv1.y, acc.y);
        acc.z = fmaf(ea1, xv1.z, acc.z); acc.w = fmaf(ea1, xv1.w, acc.w);
        acc.x = fmaf(ea2, xv2.x, acc.x); acc.y = fmaf(ea2, xv2.y, acc.y);
        acc.z = fmaf(ea2, xv2.z, acc.z); acc.w = fmaf(ea2, xv2.w, acc.w);
        acc.x = fmaf(ea3, xv3.x, acc.x); acc.y = fmaf(ea3, xv3.y, acc.y);
        acc.z = fmaf(ea3, xv3.z, acc.z); acc.w = fmaf(ea3, xv3.w, acc.w);
    }
    for (; j < end; j++) {
        int s0 = g_srcs[j];
        float t0 = 0.f;
        if (l < HH) t0 = g_as[s0 * HH + l] + adv;
        t0 = t0 > 0.f ? t0 : 0.2f * t0;
        float e0 = __expf(t0);
        if (l >= HH) e0 = 0.f;
        dsum += e0;
        float ea0 = __shfl_sync(0xffffffffu, e0, l >> 2);
        float4 xv0 = ((const float4*)(x + s0 * FF))[fq];
        acc.x = fmaf(ea0, xv0.x, acc.x); acc.y = fmaf(ea0, xv0.y, acc.y);
        acc.z = fmaf(ea0, xv0.z, acc.z); acc.w = fmaf(ea0, xv0.w, acc.w);
    }

    float dinv = 1.f / dsum;                         // lanes 0..7 valid
    float invh = __shfl_sync(0xffffffffu, dinv, l >> 2);
    acc.x *= invh; acc.y *= invh; acc.z *= invh; acc.w *= invh;

    int route = route_vec[dst];
    red4(&g_ragg[g][route * (HH * FF) + 4 * l], acc);
}

// ---------------- per-route: apply W, bias, then W_head slice ---------------
// sA[c] = sum_f ragg[r][h(c)*16+f] * W[f*512 + c] + cnt*bias[c]
// U[which][r][k] = sA . W_head[which*512 .. , k]
__global__ void k_U(const float* __restrict__ W, const float* __restrict__ bias,
                    const float* __restrict__ Whead) {
    __shared__ float sA[HC];
    __shared__ float sR[HH * FF];
    int b = blockIdx.x;
    int which = b & 1;
    int r     = b >> 1;
    int t = threadIdx.x;
    float cnt = (float)g_cnt[which][r];
    if (t < HH * FF) sR[t] = g_ragg[which][r * (HH * FF) + t];
    __syncthreads();
    for (int c = t; c < HC; c += blockDim.x) {
        int h = c >> 6;
        float acc = cnt * bias[c];
        #pragma unroll
        for (int f = 0; f < FF; f++)
            acc = fmaf(sR[h * FF + f], W[f * HC + c], acc);
        sA[c] = acc;
    }
    __syncthreads();
    if (t < KOUT) {
        float acc = 0.f;
        for (int c = 0; c < HC; c++)
            acc = fmaf(sA[c], Whead[(size_t)(which * HC + c) * WCOL + t], acc);
        g_U[which][r * 64 + t] = acc;
    }
}

// ---------------- logits -----------------------------------------------------
__global__ void k_logits(const float* __restrict__ bh) {
    int i = blockIdx.x * blockDim.x + threadIdx.x;
    if (i >= NLOG) return;
    int k  = i % KOUT;
    int r2 = (i / KOUT) % RR;
    int r1 = i / (KOUT * RR);
    g_logits[i] = g_U[0][r1 * 64 + k] + g_U[1][r2 * 64 + k] + bh[k];
}

// ---------------- global softmax --------------------------------------------
__global__ void k_softmax(float* __restrict__ out) {
    __shared__ float s[1024];
    __shared__ float gm_sh, gs_sh;
    int t = threadIdx.x;

    float m = -1e30f;
    for (int i = t; i < NLOG; i += 1024) m = fmaxf(m, g_logits[i]);
    s[t] = m; __syncthreads();
    for (int off = 512; off > 0; off >>= 1) {
        if (t < off) s[t] = fmaxf(s[t], s[t + off]);
        __syncthreads();
    }
    if (t == 0) gm_sh = s[0];
    __syncthreads();
    float gm = gm_sh;
    __syncthreads();

    float sum = 0.f;
    for (int i = t; i < NLOG; i += 1024) sum += expf(g_logits[i] - gm);
    s[t] = sum; __syncthreads();
    for (int off = 512; off > 0; off >>= 1) {
        if (t < off) s[t] += s[t + off];
        __syncthreads();
    }
    if (t == 0) gs_sh = s[0];
    __syncthreads();
    float inv = 1.f / gs_sh;

    for (int i = t; i < NLOG; i += 1024)
        out[i] = expf(g_logits[i] - gm) * inv;
}

// ---------------- launch -----------------------------------------------------
extern "C" void kernel_launch(void* const* d_in, const int* in_sizes, int n_in,
                              void* d_out, int out_size) {
    const float* x1   = (const float*)d_in[0];
    const int*   ei1  = (const int*)  d_in[1];
    const int*   rv1  = (const int*)  d_in[3];
    const float* x2   = (const float*)d_in[5];
    const int*   ei2  = (const int*)  d_in[6];
    const int*   rv2  = (const int*)  d_in[8];
    const float* Wg   = (const float*)d_in[10];
    const float* atS  = (const float*)d_in[11];
    const float* atD  = (const float*)d_in[12];
    const float* bg   = (const float*)d_in[13];
    const float* Wh   = (const float*)d_in[14];
    const float* bh   = (const float*)d_in[15];
    float* out = (float*)d_out;

    const int TB = 256;
    const int GN  = (NN + TB - 1) / TB;
    const int GE  = (EE + TB - 1) / TB;
    const int GEP = (EP + TB - 1) / TB;
    const int GEMB = (NN + 7) / 8;

    const float* xs[2]  = { x1, x2 };
    const int*   eis[2] = { ei1, ei2 };
    const int*   rvs[2] = { rv1, rv2 };

    k_zero_all<<<(2 * RR * HH * FF + TB - 1) / TB, TB>>>();
    k_prep<<<1, FF * HH>>>(Wg, atS, atD);

    for (int g = 0; g < 2; g++) {
        k_att<<<GN, TB>>>(g, xs[g], rvs[g]);
        k_deg<<<GE, TB>>>(eis[g]);
        k_blocksum<<<NCH, 1024>>>();
        k_bscan<<<1, 1>>>();
        k_offsets<<<NCH, 1024>>>();
        k_scatter<<<GEP, TB>>>(eis[g]);
        k_emb<<<GEMB, TB>>>(g, xs[g], rvs[g]);
    }
    k_U<<<2 * RR, 128>>>(Wg, bg, Wh);
    k_logits<<<(NLOG + TB - 1) / TB, TB>>>(bh);
    k_softmax<<<1, 1024>>>(out);
    (void)in_sizes; (void)n_in; (void)out_size;
}